// round 6
// baseline (speedup 1.0000x reference)
#include <cuda_runtime.h>
#include <cuda_bf16.h>
#include <cstdint>

// ---------------------------------------------------------------------------
// MultiHeadAttentionBlock — softmax result DISCARDED => attention is LINEAR:
//   (Q K^T / 8) V == Q (K^T V / 8).
// mma.sync bf16 hi/lo split (3 MMAs) — tcgen05 unavailable (PTX target sm_103).
// ---------------------------------------------------------------------------

#define Bsz 2
#define Ssz 2048
#define Dsz 1024
#define Hsz 16
#define DKsz 64
#define NCH 32

#define NELEM (Bsz * Ssz * Dsz)
#define WELEM (Dsz * Dsz)

__device__ __nv_bfloat16 g_qh[NELEM], g_ql[NELEM];
__device__ __nv_bfloat16 g_kh[NELEM], g_kl[NELEM];
__device__ __nv_bfloat16 g_vh[NELEM], g_vl[NELEM];
__device__ __nv_bfloat16 g_wqh[WELEM], g_wql[WELEM];
__device__ __nv_bfloat16 g_wkh[WELEM], g_wkl[WELEM];
__device__ __nv_bfloat16 g_wvh[WELEM], g_wvl[WELEM];
__device__ __nv_bfloat16 g_Qh[NELEM], g_Ql[NELEM];
__device__ float g_K[NELEM];
__device__ float g_V[NELEM];
__device__ float g_Mpart[NCH * Bsz * Hsz * DKsz * DKsz];
__device__ float g_M[Bsz * Hsz * DKsz * DKsz];
__device__ __nv_bfloat16 g_WTh[Bsz * Dsz * Dsz], g_WTl[Bsz * Dsz * Dsz];

__device__ __forceinline__ void ldsm4(unsigned r[4], const __nv_bfloat16* p) {
    unsigned a = (unsigned)__cvta_generic_to_shared(p);
    asm volatile("ldmatrix.sync.aligned.m8n8.x4.shared.b16 {%0,%1,%2,%3}, [%4];\n"
                 : "=r"(r[0]), "=r"(r[1]), "=r"(r[2]), "=r"(r[3]) : "r"(a));
}

__device__ __forceinline__ void mma_bf16(float c[4], const unsigned a[4], const unsigned b[2]) {
    asm volatile("mma.sync.aligned.m16n8k16.row.col.f32.bf16.bf16.f32 "
                 "{%0,%1,%2,%3}, {%4,%5,%6,%7}, {%8,%9}, {%0,%1,%2,%3};\n"
                 : "+f"(c[0]), "+f"(c[1]), "+f"(c[2]), "+f"(c[3])
                 : "r"(a[0]), "r"(a[1]), "r"(a[2]), "r"(a[3]), "r"(b[0]), "r"(b[1]));
}

__device__ __forceinline__ void cpa16(void* dst, const void* src) {
    unsigned d = (unsigned)__cvta_generic_to_shared(dst);
    asm volatile("cp.async.cg.shared.global [%0], [%1], 16;\n" :: "r"(d), "l"(src));
}
__device__ __forceinline__ void cpa_commit() { asm volatile("cp.async.commit_group;\n"); }
__device__ __forceinline__ void cpa_wait1()  { asm volatile("cp.async.wait_group 1;\n"); }
__device__ __forceinline__ void cpa_wait0()  { asm volatile("cp.async.wait_group 0;\n"); }

__global__ __launch_bounds__(256)
void split_kernel(const float* __restrict__ x, __nv_bfloat16* __restrict__ xh,
                  __nv_bfloat16* __restrict__ xl, int n4)
{
    const int i = blockIdx.x * 256 + threadIdx.x;
    if (i >= n4) return;
    float4 v = ((const float4*)x)[i];
    __nv_bfloat16 h0 = __float2bfloat16_rn(v.x), h1 = __float2bfloat16_rn(v.y);
    __nv_bfloat16 h2 = __float2bfloat16_rn(v.z), h3 = __float2bfloat16_rn(v.w);
    ((__nv_bfloat162*)xh)[2 * i]     = __halves2bfloat162(h0, h1);
    ((__nv_bfloat162*)xh)[2 * i + 1] = __halves2bfloat162(h2, h3);
    ((__nv_bfloat162*)xl)[2 * i]     = __halves2bfloat162(
        __float2bfloat16_rn(v.x - __bfloat162float(h0)),
        __float2bfloat16_rn(v.y - __bfloat162float(h1)));
    ((__nv_bfloat162*)xl)[2 * i + 1] = __halves2bfloat162(
        __float2bfloat16_rn(v.z - __bfloat162float(h2)),
        __float2bfloat16_rn(v.w - __bfloat162float(h3)));
}

#define PITCH 40
#define ARR_H (128 * PITCH)
#define STAGE_H (4 * ARR_H)
#define GSMEM (2 * STAGE_H * 2)

__global__ __launch_bounds__(128)
void gemm_mma(const __nv_bfloat16* __restrict__ Agh, const __nv_bfloat16* __restrict__ Agl,
              const __nv_bfloat16* __restrict__ Bgh, const __nv_bfloat16* __restrict__ Bgl,
              const float* __restrict__ bias,
              float* __restrict__ Cf, __nv_bfloat16* __restrict__ Ch, __nv_bfloat16* __restrict__ Cl,
              int N, long sA, long sB, long sC)
{
    extern __shared__ __align__(16) __nv_bfloat16 smem[];
    const int K = Dsz;

    Agh += (long)blockIdx.z * sA; Agl += (long)blockIdx.z * sA;
    Bgh += (long)blockIdx.z * sB; Bgl += (long)blockIdx.z * sB;
    const int bm = blockIdx.y * 128, bn = blockIdx.x * 128;
    const int tid = threadIdx.x, lane = tid & 31, warp = tid >> 5;
    const int wm = warp >> 1, wn = warp & 1;

    float acc[4][8][4];
    #pragma unroll
    for (int mt = 0; mt < 4; mt++)
        #pragma unroll
        for (int nt = 0; nt < 8; nt++)
            #pragma unroll
            for (int e = 0; e < 4; e++) acc[mt][nt][e] = 0.f;

    auto load_stage = [&](int buf, int k0) {
        __nv_bfloat16* S = smem + buf * STAGE_H;
        #pragma unroll
        for (int it = 0; it < 4; it++) {
            const int idx = tid + it * 128;
            const int r = idx >> 2, c = (idx & 3) * 8;
            const long ga = (long)(bm + r) * K + k0 + c;
            const long gb = (long)(bn + r) * K + k0 + c;
            __nv_bfloat16* row = S + r * PITCH + c;
            cpa16(row,             Agh + ga);
            cpa16(row + ARR_H,     Agl + ga);
            cpa16(row + 2 * ARR_H, Bgh + gb);
            cpa16(row + 3 * ARR_H, Bgl + gb);
        }
        cpa_commit();
    };

    load_stage(0, 0);
    load_stage(1, 32);

    const int NS = K / 32;
    for (int i = 0; i < NS; i++) {
        if (i == NS - 1) cpa_wait0(); else cpa_wait1();
        __syncthreads();

        const __nv_bfloat16* S = smem + (i & 1) * STAGE_H;
        const __nv_bfloat16* sAh = S;
        const __nv_bfloat16* sAl = S + ARR_H;
        const __nv_bfloat16* sBh = S + 2 * ARR_H;
        const __nv_bfloat16* sBl = S + 3 * ARR_H;

        #pragma unroll
        for (int kk = 0; kk < 32; kk += 16) {
            unsigned aH[4][4], aL[4][4];
            const int arow = wm * 64 + (lane & 15);
            const int acol = kk + (lane >> 4) * 8;
            #pragma unroll
            for (int mt = 0; mt < 4; mt++) {
                ldsm4(aH[mt], sAh + (arow + mt * 16) * PITCH + acol);
                ldsm4(aL[mt], sAl + (arow + mt * 16) * PITCH + acol);
            }
            const int g = lane >> 3;
            #pragma unroll
            for (int half = 0; half < 2; half++) {
                unsigned bH[4][2], bL[4][2];
                #pragma unroll
                for (int p = 0; p < 2; p++) {
                    const int brow = wn * 64 + half * 32 + p * 16 + ((g >> 1) << 3) + (lane & 7);
                    const int bcol = kk + (g & 1) * 8;
                    unsigned t[4];
                    ldsm4(t, sBh + brow * PITCH + bcol);
                    bH[2 * p][0] = t[0]; bH[2 * p][1] = t[1];
                    bH[2 * p + 1][0] = t[2]; bH[2 * p + 1][1] = t[3];
                    ldsm4(t, sBl + brow * PITCH + bcol);
                    bL[2 * p][0] = t[0]; bL[2 * p][1] = t[1];
                    bL[2 * p + 1][0] = t[2]; bL[2 * p + 1][1] = t[3];
                }
                #pragma unroll
                for (int mt = 0; mt < 4; mt++)
                    #pragma unroll
                    for (int nn = 0; nn < 4; nn++) {
                        const int nt = half * 4 + nn;
                        mma_bf16(acc[mt][nt], aH[mt], bH[nn]);
                        mma_bf16(acc[mt][nt], aH[mt], bL[nn]);
                        mma_bf16(acc[mt][nt], aL[mt], bH[nn]);
                    }
            }
        }
        __syncthreads();
        if (i + 2 < NS) load_stage(i & 1, (i + 2) * 32);
    }

    const int crow = bm + wm * 64 + lane / 4;
    const int ccol0 = bn + wn * 64 + (lane % 4) * 2;
    #pragma unroll
    for (int mt = 0; mt < 4; mt++) {
        #pragma unroll
        for (int nt = 0; nt < 8; nt++) {
            const int col = ccol0 + nt * 8;
            const float2 bb = *(const float2*)(bias + col);
            const int r0 = crow + mt * 16;
            const float o00 = acc[mt][nt][0] + bb.x, o01 = acc[mt][nt][1] + bb.y;
            const float o10 = acc[mt][nt][2] + bb.x, o11 = acc[mt][nt][3] + bb.y;
            if (Cf) {
                float* Cz = Cf + (long)blockIdx.z * sC;
                *(float2*)(Cz + (long)r0 * N + col) = make_float2(o00, o01);
                *(float2*)(Cz + (long)(r0 + 8) * N + col) = make_float2(o10, o11);
            } else {
                __nv_bfloat16* Chz = Ch + (long)blockIdx.z * sC;
                __nv_bfloat16* Clz = Cl + (long)blockIdx.z * sC;
                __nv_bfloat16 h00 = __float2bfloat16_rn(o00), h01 = __float2bfloat16_rn(o01);
                __nv_bfloat16 h10 = __float2bfloat16_rn(o10), h11 = __float2bfloat16_rn(o11);
                *(__nv_bfloat162*)(Chz + (long)r0 * N + col) = __halves2bfloat162(h00, h01);
                *(__nv_bfloat162*)(Chz + (long)(r0 + 8) * N + col) = __halves2bfloat162(h10, h11);
                *(__nv_bfloat162*)(Clz + (long)r0 * N + col) = __halves2bfloat162(
                    __float2bfloat16_rn(o00 - __bfloat162float(h00)),
                    __float2bfloat16_rn(o01 - __bfloat162float(h01)));
                *(__nv_bfloat162*)(Clz + (long)(r0 + 8) * N + col) = __halves2bfloat162(
                    __float2bfloat16_rn(o10 - __bfloat162float(h10)),
                    __float2bfloat16_rn(o11 - __bfloat162float(h11)));
            }
        }
    }
}

__global__ __launch_bounds__(256)
void ktv_kernel(const float* __restrict__ Kp, const float* __restrict__ Vp,
                float* __restrict__ Mpart)
{
    __shared__ float Ks[32][64];
    __shared__ float Vs[32][64];
    const int bh = blockIdx.x;
    const int b = bh >> 4, h = bh & 15;
    const int chunk = blockIdx.y;
    const int tid = threadIdx.x;
    const int ti = (tid >> 4) * 4, tj = (tid & 15) * 4;
    const size_t base = (size_t)b * Ssz * Dsz + h * DKsz;

    float acc[4][4] = {};
    const int s_begin = chunk * (Ssz / NCH);
    for (int s0 = s_begin; s0 < s_begin + Ssz / NCH; s0 += 32) {
        #pragma unroll
        for (int it = 0; it < 2; it++) {
            const int idx = tid + it * 256;
            const int srow = idx >> 4, scol = (idx & 15) << 2;
            *(float4*)&Ks[srow][scol] = *(const float4*)(Kp + base + (size_t)(s0 + srow) * Dsz + scol);
            *(float4*)&Vs[srow][scol] = *(const float4*)(Vp + base + (size_t)(s0 + srow) * Dsz + scol);
        }
        __syncthreads();
        #pragma unroll
        for (int ss = 0; ss < 32; ss++) {
            float4 ka = *(const float4*)&Ks[ss][ti];
            float4 vb = *(const float4*)&Vs[ss][tj];
            const float a[4] = {ka.x, ka.y, ka.z, ka.w};
            const float w[4] = {vb.x, vb.y, vb.z, vb.w};
            #pragma unroll
            for (int i = 0; i < 4; i++)
                #pragma unroll
                for (int j = 0; j < 4; j++) acc[i][j] += a[i] * w[j];
        }
        __syncthreads();
    }
    float* outp = Mpart + (long)chunk * (Bsz * Hsz * DKsz * DKsz) + (long)bh * (DKsz * DKsz);
    #pragma unroll
    for (int i = 0; i < 4; i++)
        *(float4*)(outp + (ti + i) * DKsz + tj) = make_float4(acc[i][0], acc[i][1], acc[i][2], acc[i][3]);
}

__global__ __launch_bounds__(256)
void ktv_reduce(const float* __restrict__ Mpart, float* __restrict__ Mout)
{
    const int idx = blockIdx.x * 256 + threadIdx.x;
    float s = 0.f;
    #pragma unroll
    for (int c = 0; c < NCH; c++)
        s += Mpart[(long)c * (Bsz * Hsz * DKsz * DKsz) + idx];
    Mout[idx] = s * 0.125f;
}

__global__ __launch_bounds__(256)
void wcomb_kernel(const float* __restrict__ Mh, const float* __restrict__ Wo,
                  __nv_bfloat16* __restrict__ WTh, __nv_bfloat16* __restrict__ WTl)
{
    __shared__ float MshT[64 * 64];
    __shared__ float WoSh[32][64];
    const int c0 = blockIdx.x * 32;
    const int h = blockIdx.y, b = blockIdx.z;
    const int tid = threadIdx.x;

    const float* Mp = Mh + (size_t)(b * Hsz + h) * (DKsz * DKsz);
    #pragma unroll
    for (int t = tid; t < 4096; t += 256) {
        const int i = t >> 6, j = t & 63;
        MshT[j * 64 + i] = Mp[t];
    }
    #pragma unroll
    for (int t = tid; t < 2048; t += 256) {
        const int cc = t >> 6, j = t & 63;
        WoSh[cc][j] = Wo[(size_t)(c0 + cc) * Dsz + h * DKsz + j];
    }
    __syncthreads();

    const int cc = tid >> 3;
    const int i0 = (tid & 7) * 8;
    float acc[8] = {};
    #pragma unroll
    for (int j = 0; j < 64; j++) {
        const float w = WoSh[cc][j];
        #pragma unroll
        for (int u = 0; u < 8; u++) acc[u] += w * MshT[j * 64 + i0 + u];
    }
    const long off = (long)(b * Dsz + c0 + cc) * Dsz + h * DKsz + i0;
    #pragma unroll
    for (int u = 0; u < 8; u += 2) {
        __nv_bfloat16 h0 = __float2bfloat16_rn(acc[u]);
        __nv_bfloat16 h1 = __float2bfloat16_rn(acc[u + 1]);
        *(__nv_bfloat162*)(WTh + off + u) = __halves2bfloat162(h0, h1);
        *(__nv_bfloat162*)(WTl + off + u) = __halves2bfloat162(
            __float2bfloat16_rn(acc[u] - __bfloat162float(h0)),
            __float2bfloat16_rn(acc[u + 1] - __bfloat162float(h1)));
    }
}

extern "C" void kernel_launch(void* const* d_in, const int* in_sizes, int n_in,
                              void* d_out, int out_size)
{
    const float* q  = (const float*)d_in[0];
    const float* k  = (const float*)d_in[1];
    const float* v  = (const float*)d_in[2];
    const float* wq = (const float*)d_in[3];
    const float* bq = (const float*)d_in[4];
    const float* wk = (const float*)d_in[5];
    const float* bk = (const float*)d_in[6];
    const float* wv = (const float*)d_in[7];
    const float* bv = (const float*)d_in[8];
    const float* wo = (const float*)d_in[9];
    const float* bo = (const float*)d_in[10];
    float* out = (float*)d_out;

    __nv_bfloat16 *qh, *ql, *kh, *kl, *vh, *vl;
    __nv_bfloat16 *wqh, *wql, *wkh, *wkl, *wvh, *wvl;
    __nv_bfloat16 *Qh, *Ql, *WTh, *WTl;
    float *K, *V, *Mp, *Mb;
    cudaGetSymbolAddress((void**)&qh, g_qh);   cudaGetSymbolAddress((void**)&ql, g_ql);
    cudaGetSymbolAddress((void**)&kh, g_kh);   cudaGetSymbolAddress((void**)&kl, g_kl);
    cudaGetSymbolAddress((void**)&vh, g_vh);   cudaGetSymbolAddress((void**)&vl, g_vl);
    cudaGetSymbolAddress((void**)&wqh, g_wqh); cudaGetSymbolAddress((void**)&wql, g_wql);
    cudaGetSymbolAddress((void**)&wkh, g_wkh); cudaGetSymbolAddress((void**)&wkl, g_wkl);
    cudaGetSymbolAddress((void**)&wvh, g_wvh); cudaGetSymbolAddress((void**)&wvl, g_wvl);
    cudaGetSymbolAddress((void**)&Qh, g_Qh);   cudaGetSymbolAddress((void**)&Ql, g_Ql);
    cudaGetSymbolAddress((void**)&K, g_K);     cudaGetSymbolAddress((void**)&V, g_V);
    cudaGetSymbolAddress((void**)&Mp, g_Mpart);
    cudaGetSymbolAddress((void**)&Mb, g_M);
    cudaGetSymbolAddress((void**)&WTh, g_WTh); cudaGetSymbolAddress((void**)&WTl, g_WTl);

    static int smem_set = 0;
    if (!smem_set) {
        cudaFuncSetAttribute(gemm_mma, cudaFuncAttributeMaxDynamicSharedMemorySize, GSMEM);
        smem_set = 1;
    }

    split_kernel<<<NELEM / 4 / 256, 256>>>(q, qh, ql, NELEM / 4);
    split_kernel<<<NELEM / 4 / 256, 256>>>(k, kh, kl, NELEM / 4);
    split_kernel<<<NELEM / 4 / 256, 256>>>(v, vh, vl, NELEM / 4);
    split_kernel<<<WELEM / 4 / 256, 256>>>(wq, wqh, wql, WELEM / 4);
    split_kernel<<<WELEM / 4 / 256, 256>>>(wk, wkh, wkl, WELEM / 4);
    split_kernel<<<WELEM / 4 / 256, 256>>>(wv, wvh, wvl, WELEM / 4);

    const dim3 gp(Dsz / 128, (Bsz * Ssz) / 128, 1);
    gemm_mma<<<gp, 128, GSMEM>>>(qh, ql, wqh, wql, bq, nullptr, Qh, Ql, Dsz, 0, 0, 0);
    gemm_mma<<<gp, 128, GSMEM>>>(kh, kl, wkh, wkl, bk, K, nullptr, nullptr, Dsz, 0, 0, 0);
    gemm_mma<<<gp, 128, GSMEM>>>(vh, vl, wvh, wvl, bv, V, nullptr, nullptr, Dsz, 0, 0, 0);

    ktv_kernel<<<dim3(Bsz * Hsz, NCH), 256>>>(K, V, Mp);
    ktv_reduce<<<(Bsz * Hsz * DKsz * DKsz) / 256, 256>>>(Mp, Mb);

    wcomb_kernel<<<dim3(Dsz / 32, Hsz, Bsz), 256>>>(Mb, wo, WTh, WTl);

    gemm_mma<<<dim3(Dsz / 128, Ssz / 128, Bsz), 128, GSMEM>>>(
        Qh, Ql, WTh, WTl, bo, out, nullptr, nullptr,
        Dsz, (long)Ssz * Dsz, (long)Dsz * Dsz, (long)Ssz * Dsz);
}

// round 7
// speedup vs baseline: 1.0083x; 1.0083x over previous
#include <cuda_runtime.h>
#include <cuda_bf16.h>
#include <cstdint>

// ---------------------------------------------------------------------------
// MultiHeadAttentionBlock — softmax DISCARDED => fully linear. Algebraic fold:
//   X2_b = v_b^T k_b                         (NT, K=2048)        8.6 GF
//   Z_b  = Wk @ X2_b^T                       (NT, K=1024)        4.3 GF
//   M[b,h] = (1/8)[(Z Wv^T)[hblk] + (Wk sk) bv^T + bk (Wv sv)^T + S bk bv^T]
//   WT[b][c][o] = sum_j M Wo ;  b' = bq WT^T + bo
//   G_b  = WT_b @ Wq                         (NT, K=1024)        4.3 GF
//   out_b = q_b @ G_b^T + b'                 (NT, K=1024)        8.6 GF
// Heavy GEMMs: bf16 hi/lo split (3 MMAs each) on mma.sync.
// ---------------------------------------------------------------------------

#define Bsz 2
#define Ssz 2048
#define Dsz 1024
#define Hsz 16
#define DKsz 64
#define SCH 16     // S-chunks for colsum

#define NELEM (Bsz * Ssz * Dsz)
#define WELEM (Dsz * Dsz)
#define BDD   (Bsz * Dsz * Dsz)
#define MELEM (Bsz * Hsz * DKsz * DKsz)

__device__ __nv_bfloat16 g_qh[NELEM], g_ql[NELEM];
__device__ __nv_bfloat16 g_kTh[NELEM], g_kTl[NELEM];     // [B][D][S]
__device__ __nv_bfloat16 g_vTh[NELEM], g_vTl[NELEM];     // [B][D][S]
__device__ __nv_bfloat16 g_wkh[WELEM], g_wkl[WELEM];
__device__ __nv_bfloat16 g_wqTh[WELEM], g_wqTl[WELEM];   // Wq^T [d][o]
__device__ __nv_bfloat16 g_Xh[BDD], g_Xl[BDD];           // X2
__device__ float g_Z[BDD];
__device__ float g_skpart[SCH * Bsz * Dsz], g_svpart[SCH * Bsz * Dsz];
__device__ float g_sk[Bsz * Dsz], g_sv[Bsz * Dsz];
__device__ float g_wksk[Bsz * Dsz], g_wvsv[Bsz * Dsz];
__device__ float g_Mpart[4 * MELEM];
__device__ float g_M[MELEM];
__device__ __nv_bfloat16 g_WTh[BDD], g_WTl[BDD];
__device__ __nv_bfloat16 g_Gh[BDD], g_Gl[BDD];
__device__ float g_bp[Bsz * Dsz];
__device__ float g_zeros[Dsz];   // zero-initialized, never written

// ---------------------------------------------------------------------------
__device__ __forceinline__ void ldsm4(unsigned r[4], const __nv_bfloat16* p) {
    unsigned a = (unsigned)__cvta_generic_to_shared(p);
    asm volatile("ldmatrix.sync.aligned.m8n8.x4.shared.b16 {%0,%1,%2,%3}, [%4];\n"
                 : "=r"(r[0]), "=r"(r[1]), "=r"(r[2]), "=r"(r[3]) : "r"(a));
}
__device__ __forceinline__ void mma_bf16(float c[4], const unsigned a[4], const unsigned b[2]) {
    asm volatile("mma.sync.aligned.m16n8k16.row.col.f32.bf16.bf16.f32 "
                 "{%0,%1,%2,%3}, {%4,%5,%6,%7}, {%8,%9}, {%0,%1,%2,%3};\n"
                 : "+f"(c[0]), "+f"(c[1]), "+f"(c[2]), "+f"(c[3])
                 : "r"(a[0]), "r"(a[1]), "r"(a[2]), "r"(a[3]), "r"(b[0]), "r"(b[1]));
}
__device__ __forceinline__ void cpa16(void* dst, const void* src) {
    unsigned d = (unsigned)__cvta_generic_to_shared(dst);
    asm volatile("cp.async.cg.shared.global [%0], [%1], 16;\n" :: "r"(d), "l"(src));
}
__device__ __forceinline__ void cpa_commit() { asm volatile("cp.async.commit_group;\n"); }
__device__ __forceinline__ void cpa_wait1()  { asm volatile("cp.async.wait_group 1;\n"); }
__device__ __forceinline__ void cpa_wait0()  { asm volatile("cp.async.wait_group 0;\n"); }

// ---------------------------------------------------------------------------
__global__ __launch_bounds__(256)
void split_kernel(const float* __restrict__ x, __nv_bfloat16* __restrict__ xh,
                  __nv_bfloat16* __restrict__ xl, int n4)
{
    const int i = blockIdx.x * 256 + threadIdx.x;
    if (i >= n4) return;
    float4 v = ((const float4*)x)[i];
    __nv_bfloat16 h0 = __float2bfloat16_rn(v.x), h1 = __float2bfloat16_rn(v.y);
    __nv_bfloat16 h2 = __float2bfloat16_rn(v.z), h3 = __float2bfloat16_rn(v.w);
    ((__nv_bfloat162*)xh)[2 * i]     = __halves2bfloat162(h0, h1);
    ((__nv_bfloat162*)xh)[2 * i + 1] = __halves2bfloat162(h2, h3);
    ((__nv_bfloat162*)xl)[2 * i]     = __halves2bfloat162(
        __float2bfloat16_rn(v.x - __bfloat162float(h0)),
        __float2bfloat16_rn(v.y - __bfloat162float(h1)));
    ((__nv_bfloat162*)xl)[2 * i + 1] = __halves2bfloat162(
        __float2bfloat16_rn(v.z - __bfloat162float(h2)),
        __float2bfloat16_rn(v.w - __bfloat162float(h3)));
}

// Transpose + split: X[z][R][C] -> T[z][C][R] bf16 hi/lo
__global__ __launch_bounds__(256)
void tsplit_kernel(const float* __restrict__ X, __nv_bfloat16* __restrict__ Th,
                   __nv_bfloat16* __restrict__ Tl, int R, int C)
{
    __shared__ float sm[32][33];
    const int c0 = blockIdx.x * 32, r0 = blockIdx.y * 32;
    const long z = (long)blockIdx.z * R * C;
    const int tx = threadIdx.x & 31, ty = threadIdx.x >> 5;
    #pragma unroll
    for (int i = 0; i < 4; i++)
        sm[ty + i * 8][tx] = X[z + (long)(r0 + ty + i * 8) * C + c0 + tx];
    __syncthreads();
    #pragma unroll
    for (int i = 0; i < 4; i++) {
        const float v = sm[tx][ty + i * 8];
        const __nv_bfloat16 h = __float2bfloat16_rn(v);
        const long o = z + (long)(c0 + ty + i * 8) * R + r0 + tx;
        Th[o] = h;
        Tl[o] = __float2bfloat16_rn(v - __bfloat162float(h));
    }
}

// Column-sum partials: grid (D/256, SCH, B)
__global__ __launch_bounds__(256)
void colsum_part(const float* __restrict__ k, const float* __restrict__ v,
                 float* __restrict__ skp, float* __restrict__ svp)
{
    const int d = blockIdx.x * 256 + threadIdx.x;
    const int ch = blockIdx.y, b = blockIdx.z;
    const long base = (long)b * Ssz * Dsz + (long)(ch * (Ssz / SCH)) * Dsz + d;
    float a = 0.f, c = 0.f;
    #pragma unroll 4
    for (int s = 0; s < Ssz / SCH; s++) {
        a += k[base + (long)s * Dsz];
        c += v[base + (long)s * Dsz];
    }
    skp[((long)ch * Bsz + b) * Dsz + d] = a;
    svp[((long)ch * Bsz + b) * Dsz + d] = c;
}

__global__ __launch_bounds__(256)
void colsum_reduce(const float* __restrict__ skp, const float* __restrict__ svp,
                   float* __restrict__ sk, float* __restrict__ sv)
{
    const int i = blockIdx.x * 256 + threadIdx.x;   // 0..B*D-1
    float a = 0.f, c = 0.f;
    #pragma unroll
    for (int ch = 0; ch < SCH; ch++) {
        a += skp[(long)ch * Bsz * Dsz + i];
        c += svp[(long)ch * Bsz * Dsz + i];
    }
    sk[i] = a; sv[i] = c;
}

// wksk[b] = Wk @ sk_b ; wvsv[b] = Wv @ sv_b.  grid (D, 2, B), 128 thr
__global__ __launch_bounds__(128)
void matvec_kernel(const float* __restrict__ wk, const float* __restrict__ wv,
                   const float* __restrict__ sk, const float* __restrict__ sv,
                   float* __restrict__ wksk, float* __restrict__ wvsv)
{
    const int o = blockIdx.x, which = blockIdx.y, b = blockIdx.z;
    const float* W = which ? wv : wk;
    const float* s = (which ? sv : sk) + b * Dsz;
    float p = 0.f;
    for (int d = threadIdx.x; d < Dsz; d += 128) p += W[(long)o * Dsz + d] * s[d];
    #pragma unroll
    for (int off = 16; off; off >>= 1) p += __shfl_down_sync(0xffffffff, p, off);
    __shared__ float red[4];
    if ((threadIdx.x & 31) == 0) red[threadIdx.x >> 5] = p;
    __syncthreads();
    if (threadIdx.x == 0)
        (which ? wvsv : wksk)[b * Dsz + o] = red[0] + red[1] + red[2] + red[3];
}

// ---------------------------------------------------------------------------
// Tensor-core GEMM (NT + bias, batched, bf16 hi/lo, 3-MMA):
//   C[z][M,N] = A[z][M,K] @ B[z][N,K]^T + bias[z][N]
// CTA 128x128, BK=32, 4 warps (64x64 warp tile), cp.async 2-stage.
// ---------------------------------------------------------------------------
#define PITCH 40
#define ARR_H (128 * PITCH)
#define STAGE_H (4 * ARR_H)
#define GSMEM (2 * STAGE_H * 2)

__global__ __launch_bounds__(128)
void gemm_mma(const __nv_bfloat16* __restrict__ Agh, const __nv_bfloat16* __restrict__ Agl,
              const __nv_bfloat16* __restrict__ Bgh, const __nv_bfloat16* __restrict__ Bgl,
              const float* __restrict__ bias,
              float* __restrict__ Cf, __nv_bfloat16* __restrict__ Ch, __nv_bfloat16* __restrict__ Cl,
              int N, int K, long sA, long sB, long sC, long sBias)
{
    extern __shared__ __align__(16) __nv_bfloat16 smem[];

    Agh += (long)blockIdx.z * sA; Agl += (long)blockIdx.z * sA;
    Bgh += (long)blockIdx.z * sB; Bgl += (long)blockIdx.z * sB;
    bias += (long)blockIdx.z * sBias;
    const int bm = blockIdx.y * 128, bn = blockIdx.x * 128;
    const int tid = threadIdx.x, lane = tid & 31, warp = tid >> 5;
    const int wm = warp >> 1, wn = warp & 1;

    float acc[4][8][4];
    #pragma unroll
    for (int mt = 0; mt < 4; mt++)
        #pragma unroll
        for (int nt = 0; nt < 8; nt++)
            #pragma unroll
            for (int e = 0; e < 4; e++) acc[mt][nt][e] = 0.f;

    auto load_stage = [&](int buf, int k0) {
        __nv_bfloat16* S = smem + buf * STAGE_H;
        #pragma unroll
        for (int it = 0; it < 4; it++) {
            const int idx = tid + it * 128;
            const int r = idx >> 2, c = (idx & 3) * 8;
            const long ga = (long)(bm + r) * K + k0 + c;
            const long gb = (long)(bn + r) * K + k0 + c;
            __nv_bfloat16* row = S + r * PITCH + c;
            cpa16(row,             Agh + ga);
            cpa16(row + ARR_H,     Agl + ga);
            cpa16(row + 2 * ARR_H, Bgh + gb);
            cpa16(row + 3 * ARR_H, Bgl + gb);
        }
        cpa_commit();
    };

    load_stage(0, 0);
    load_stage(1, 32);

    const int NS = K / 32;
    for (int i = 0; i < NS; i++) {
        if (i == NS - 1) cpa_wait0(); else cpa_wait1();
        __syncthreads();

        const __nv_bfloat16* S = smem + (i & 1) * STAGE_H;
        const __nv_bfloat16* sAh = S;
        const __nv_bfloat16* sAl = S + ARR_H;
        const __nv_bfloat16* sBh = S + 2 * ARR_H;
        const __nv_bfloat16* sBl = S + 3 * ARR_H;

        #pragma unroll
        for (int kk = 0; kk < 32; kk += 16) {
            unsigned aH[4][4], aL[4][4];
            const int arow = wm * 64 + (lane & 15);
            const int acol = kk + (lane >> 4) * 8;
            #pragma unroll
            for (int mt = 0; mt < 4; mt++) {
                ldsm4(aH[mt], sAh + (arow + mt * 16) * PITCH + acol);
                ldsm4(aL[mt], sAl + (arow + mt * 16) * PITCH + acol);
            }
            const int g = lane >> 3;
            #pragma unroll
            for (int half = 0; half < 2; half++) {
                unsigned bH[4][2], bL[4][2];
                #pragma unroll
                for (int p = 0; p < 2; p++) {
                    const int brow = wn * 64 + half * 32 + p * 16 + ((g >> 1) << 3) + (lane & 7);
                    const int bcol = kk + (g & 1) * 8;
                    unsigned t[4];
                    ldsm4(t, sBh + brow * PITCH + bcol);
                    bH[2 * p][0] = t[0]; bH[2 * p][1] = t[1];
                    bH[2 * p + 1][0] = t[2]; bH[2 * p + 1][1] = t[3];
                    ldsm4(t, sBl + brow * PITCH + bcol);
                    bL[2 * p][0] = t[0]; bL[2 * p][1] = t[1];
                    bL[2 * p + 1][0] = t[2]; bL[2 * p + 1][1] = t[3];
                }
                #pragma unroll
                for (int mt = 0; mt < 4; mt++)
                    #pragma unroll
                    for (int nn = 0; nn < 4; nn++) {
                        const int nt = half * 4 + nn;
                        mma_bf16(acc[mt][nt], aH[mt], bH[nn]);
                        mma_bf16(acc[mt][nt], aH[mt], bL[nn]);
                        mma_bf16(acc[mt][nt], aL[mt], bH[nn]);
                    }
            }
        }
        __syncthreads();
        if (i + 2 < NS) load_stage(i & 1, (i + 2) * 32);
    }

    const int crow = bm + wm * 64 + lane / 4;
    const int ccol0 = bn + wn * 64 + (lane % 4) * 2;
    #pragma unroll
    for (int mt = 0; mt < 4; mt++) {
        #pragma unroll
        for (int nt = 0; nt < 8; nt++) {
            const int col = ccol0 + nt * 8;
            const float2 bb = *(const float2*)(bias + col);
            const int r0 = crow + mt * 16;
            const float o00 = acc[mt][nt][0] + bb.x, o01 = acc[mt][nt][1] + bb.y;
            const float o10 = acc[mt][nt][2] + bb.x, o11 = acc[mt][nt][3] + bb.y;
            if (Cf) {
                float* Cz = Cf + (long)blockIdx.z * sC;
                *(float2*)(Cz + (long)r0 * N + col) = make_float2(o00, o01);
                *(float2*)(Cz + (long)(r0 + 8) * N + col) = make_float2(o10, o11);
            } else {
                __nv_bfloat16* Chz = Ch + (long)blockIdx.z * sC;
                __nv_bfloat16* Clz = Cl + (long)blockIdx.z * sC;
                __nv_bfloat16 h00 = __float2bfloat16_rn(o00), h01 = __float2bfloat16_rn(o01);
                __nv_bfloat16 h10 = __float2bfloat16_rn(o10), h11 = __float2bfloat16_rn(o11);
                *(__nv_bfloat162*)(Chz + (long)r0 * N + col) = __halves2bfloat162(h00, h01);
                *(__nv_bfloat162*)(Chz + (long)(r0 + 8) * N + col) = __halves2bfloat162(h10, h11);
                *(__nv_bfloat162*)(Clz + (long)r0 * N + col) = __halves2bfloat162(
                    __float2bfloat16_rn(o00 - __bfloat162float(h00)),
                    __float2bfloat16_rn(o01 - __bfloat162float(h01)));
                *(__nv_bfloat162*)(Clz + (long)(r0 + 8) * N + col) = __halves2bfloat162(
                    __float2bfloat16_rn(o10 - __bfloat162float(h10)),
                    __float2bfloat16_rn(o11 - __bfloat162float(h11)));
            }
        }
    }
}

// ---------------------------------------------------------------------------
// M partials: part[ch][b,h][i][j] = sum_{e in chunk} Z[b][h*64+i][e]*Wv[h*64+j][e]
// grid (B*H, 4), 256 threads (16x16, 4x4 outputs each).
// ---------------------------------------------------------------------------
__global__ __launch_bounds__(256)
void mfold_part(const float* __restrict__ Z, const float* __restrict__ wv,
                float* __restrict__ part)
{
    __shared__ float Zs[64][33];
    __shared__ float Ws[64][33];
    const int bh = blockIdx.x;
    const int b = bh >> 4, h = bh & 15;
    const int chunk = blockIdx.y;
    const int tid = threadIdx.x;
    const int ti = (tid >> 4) * 4, tj = (tid & 15) * 4;
    const long zbase = (long)b * Dsz * Dsz + (long)(h * DKsz) * Dsz;
    const long wbase = (long)(h * DKsz) * Dsz;

    float acc[4][4] = {};
    for (int e0 = chunk * 256; e0 < chunk * 256 + 256; e0 += 32) {
        #pragma unroll
        for (int it = 0; it < 2; it++) {
            const int s = tid + it * 256;
            const int row = s >> 3, c4 = (s & 7) * 4;
            float4 zv = *(const float4*)(Z + zbase + (long)row * Dsz + e0 + c4);
            Zs[row][c4] = zv.x; Zs[row][c4+1] = zv.y; Zs[row][c4+2] = zv.z; Zs[row][c4+3] = zv.w;
            float4 wvv = *(const float4*)(wv + wbase + (long)row * Dsz + e0 + c4);
            Ws[row][c4] = wvv.x; Ws[row][c4+1] = wvv.y; Ws[row][c4+2] = wvv.z; Ws[row][c4+3] = wvv.w;
        }
        __syncthreads();
        #pragma unroll
        for (int ee = 0; ee < 32; ee++) {
            float a[4], w[4];
            #pragma unroll
            for (int u = 0; u < 4; u++) { a[u] = Zs[ti + u][ee]; w[u] = Ws[tj + u][ee]; }
            #pragma unroll
            for (int i = 0; i < 4; i++)
                #pragma unroll
                for (int j = 0; j < 4; j++) acc[i][j] += a[i] * w[j];
        }
        __syncthreads();
    }
    float* outp = part + (long)chunk * MELEM + (long)bh * (DKsz * DKsz);
    #pragma unroll
    for (int i = 0; i < 4; i++)
        #pragma unroll
        for (int j = 0; j < 4; j++)
            outp[(ti + i) * DKsz + tj + j] = acc[i][j];
}

// Reduce + rank-1 bias corrections; M = (1/8) K^T V per-head block.
__global__ __launch_bounds__(256)
void mfold_reduce(const float* __restrict__ part, const float* __restrict__ wksk,
                  const float* __restrict__ wvsv, const float* __restrict__ bk,
                  const float* __restrict__ bv, float* __restrict__ M)
{
    const int idx = blockIdx.x * 256 + threadIdx.x;
    const int b = idx >> 16;
    const int h = (idx >> 12) & 15;
    const int i = (idx >> 6) & 63;
    const int j = idx & 63;
    const int oi = h * DKsz + i, oj = h * DKsz + j;
    float s = 0.f;
    #pragma unroll
    for (int c = 0; c < 4; c++) s += part[(long)c * MELEM + idx];
    s += wksk[b * Dsz + oi] * bv[oj]
       + bk[oi] * wvsv[b * Dsz + oj]
       + (float)Ssz * bk[oi] * bv[oj];
    M[idx] = s * 0.125f;
}

// ---------------------------------------------------------------------------
// WT[b][c][h*64+i] = sum_j M[b,h][i][j] * Wo[c][h*64+j]  (emit bf16 h/l)
// ---------------------------------------------------------------------------
__global__ __launch_bounds__(256)
void wcomb_kernel(const float* __restrict__ Mh, const float* __restrict__ Wo,
                  __nv_bfloat16* __restrict__ WTh, __nv_bfloat16* __restrict__ WTl)
{
    __shared__ float MshT[64 * 64];
    __shared__ float WoSh[32][64];
    const int c0 = blockIdx.x * 32;
    const int h = blockIdx.y, b = blockIdx.z;
    const int tid = threadIdx.x;

    const float* Mp = Mh + (size_t)(b * Hsz + h) * (DKsz * DKsz);
    #pragma unroll
    for (int t = tid; t < 4096; t += 256) {
        const int i = t >> 6, j = t & 63;
        MshT[j * 64 + i] = Mp[t];
    }
    #pragma unroll
    for (int t = tid; t < 2048; t += 256) {
        const int cc = t >> 6, j = t & 63;
        WoSh[cc][j] = Wo[(size_t)(c0 + cc) * Dsz + h * DKsz + j];
    }
    __syncthreads();

    const int cc = tid >> 3;
    const int i0 = (tid & 7) * 8;
    float acc[8] = {};
    #pragma unroll
    for (int j = 0; j < 64; j++) {
        const float w = WoSh[cc][j];
        #pragma unroll
        for (int u = 0; u < 8; u++) acc[u] += w * MshT[j * 64 + i0 + u];
    }
    const long off = (long)(b * Dsz + c0 + cc) * Dsz + h * DKsz + i0;
    #pragma unroll
    for (int u = 0; u < 8; u += 2) {
        __nv_bfloat16 h0 = __float2bfloat16_rn(acc[u]);
        __nv_bfloat16 h1 = __float2bfloat16_rn(acc[u + 1]);
        *(__nv_bfloat162*)(WTh + off + u) = __halves2bfloat162(h0, h1);
        *(__nv_bfloat162*)(WTl + off + u) = __halves2bfloat162(
            __float2bfloat16_rn(acc[u] - __bfloat162float(h0)),
            __float2bfloat16_rn(acc[u + 1] - __bfloat162float(h1)));
    }
}

// b'[b][c] = sum_o bq[o] * WT[b][c][o] + bo[c]
__global__ __launch_bounds__(128)
void bprime_kernel(const __nv_bfloat16* __restrict__ WTh, const __nv_bfloat16* __restrict__ WTl,
                   const float* __restrict__ bq, const float* __restrict__ bo,
                   float* __restrict__ bp)
{
    const int c = blockIdx.x, b = blockIdx.y;
    const long base = (long)b * Dsz * Dsz + (long)c * Dsz;
    float p = 0.f;
    for (int o = threadIdx.x; o < Dsz; o += 128)
        p += bq[o] * (__bfloat162float(WTh[base + o]) + __bfloat162float(WTl[base + o]));
    #pragma unroll
    for (int off = 16; off; off >>= 1) p += __shfl_down_sync(0xffffffff, p, off);
    __shared__ float red[4];
    if ((threadIdx.x & 31) == 0) red[threadIdx.x >> 5] = p;
    __syncthreads();
    if (threadIdx.x == 0)
        bp[b * Dsz + c] = red[0] + red[1] + red[2] + red[3] + bo[c];
}

// ---------------------------------------------------------------------------
extern "C" void kernel_launch(void* const* d_in, const int* in_sizes, int n_in,
                              void* d_out, int out_size)
{
    const float* q  = (const float*)d_in[0];
    const float* k  = (const float*)d_in[1];
    const float* v  = (const float*)d_in[2];
    const float* wq = (const float*)d_in[3];
    const float* bq = (const float*)d_in[4];
    const float* wk = (const float*)d_in[5];
    const float* bk = (const float*)d_in[6];
    const float* wv = (const float*)d_in[7];
    const float* bv = (const float*)d_in[8];
    const float* wo = (const float*)d_in[9];
    const float* bo = (const float*)d_in[10];
    float* out = (float*)d_out;

    __nv_bfloat16 *qh, *ql, *kTh, *kTl, *vTh, *vTl, *wkh, *wkl, *wqTh, *wqTl;
    __nv_bfloat16 *Xh, *Xl, *WTh, *WTl, *Gh, *Gl;
    float *Z, *skp, *svp, *sk, *sv, *wksk, *wvsv, *Mp, *Mb, *bp, *zeros;
    cudaGetSymbolAddress((void**)&qh, g_qh);     cudaGetSymbolAddress((void**)&ql, g_ql);
    cudaGetSymbolAddress((void**)&kTh, g_kTh);   cudaGetSymbolAddress((void**)&kTl, g_kTl);
    cudaGetSymbolAddress((void**)&vTh, g_vTh);   cudaGetSymbolAddress((void**)&vTl, g_vTl);
    cudaGetSymbolAddress((void**)&wkh, g_wkh);   cudaGetSymbolAddress((void**)&wkl, g_wkl);
    cudaGetSymbolAddress((void**)&wqTh, g_wqTh); cudaGetSymbolAddress((void**)&wqTl, g_wqTl);
    cudaGetSymbolAddress((void**)&Xh, g_Xh);     cudaGetSymbolAddress((void**)&Xl, g_Xl);
    cudaGetSymbolAddress((void**)&Z, g_Z);
    cudaGetSymbolAddress((void**)&skp, g_skpart); cudaGetSymbolAddress((void**)&svp, g_svpart);
    cudaGetSymbolAddress((void**)&sk, g_sk);     cudaGetSymbolAddress((void**)&sv, g_sv);
    cudaGetSymbolAddress((void**)&wksk, g_wksk); cudaGetSymbolAddress((void**)&wvsv, g_wvsv);
    cudaGetSymbolAddress((void**)&Mp, g_Mpart);  cudaGetSymbolAddress((void**)&Mb, g_M);
    cudaGetSymbolAddress((void**)&WTh, g_WTh);   cudaGetSymbolAddress((void**)&WTl, g_WTl);
    cudaGetSymbolAddress((void**)&Gh, g_Gh);     cudaGetSymbolAddress((void**)&Gl, g_Gl);
    cudaGetSymbolAddress((void**)&bp, g_bp);
    cudaGetSymbolAddress((void**)&zeros, g_zeros);

    static int smem_set = 0;
    if (!smem_set) {
        cudaFuncSetAttribute(gemm_mma, cudaFuncAttributeMaxDynamicSharedMemorySize, GSMEM);
        smem_set = 1;
    }

    // 0) preprocessing
    split_kernel<<<NELEM / 4 / 256, 256>>>(q, qh, ql, NELEM / 4);
    split_kernel<<<WELEM / 4 / 256, 256>>>(wk, wkh, wkl, WELEM / 4);
    tsplit_kernel<<<dim3(Dsz / 32, Ssz / 32, Bsz), 256>>>(k, kTh, kTl, Ssz, Dsz);
    tsplit_kernel<<<dim3(Dsz / 32, Ssz / 32, Bsz), 256>>>(v, vTh, vTl, Ssz, Dsz);
    tsplit_kernel<<<dim3(Dsz / 32, Dsz / 32, 1), 256>>>(wq, wqTh, wqTl, Dsz, Dsz);
    colsum_part<<<dim3(Dsz / 256, SCH, Bsz), 256>>>(k, v, skp, svp);
    colsum_reduce<<<(Bsz * Dsz) / 256, 256>>>(skp, svp, sk, sv);
    matvec_kernel<<<dim3(Dsz, 2, Bsz), 128>>>(wk, wv, sk, sv, wksk, wvsv);

    // 1) X2_b = v_b^T k_b  [1024x1024, K=2048] -> bf16 h/l
    gemm_mma<<<dim3(Dsz / 128, Dsz / 128, Bsz), 128, GSMEM>>>(
        vTh, vTl, kTh, kTl, zeros, nullptr, Xh, Xl,
        Dsz, Ssz, (long)Dsz * Ssz, (long)Dsz * Ssz, (long)Dsz * Dsz, 0);

    // 2) Z_b = Wk @ X2_b^T  [1024x1024, K=1024] -> fp32
    gemm_mma<<<dim3(Dsz / 128, Dsz / 128, Bsz), 128, GSMEM>>>(
        wkh, wkl, Xh, Xl, zeros, Z, nullptr, nullptr,
        Dsz, Dsz, 0, (long)Dsz * Dsz, (long)Dsz * Dsz, 0);

    // 3) M blocks + bias corrections
    mfold_part<<<dim3(Bsz * Hsz, 4), 256>>>(Z, wv, Mp);
    mfold_reduce<<<MELEM / 256, 256>>>(Mp, wksk, wvsv, bk, bv, Mb);

    // 4) WT fold, b'
    wcomb_kernel<<<dim3(Dsz / 32, Hsz, Bsz), 256>>>(Mb, wo, WTh, WTl);
    bprime_kernel<<<dim3(Dsz, Bsz), 128>>>(WTh, WTl, bq, bo, bp);

    // 5) G_b = WT_b @ Wq  [1024x1024, K=1024] -> bf16 h/l
    gemm_mma<<<dim3(Dsz / 128, Dsz / 128, Bsz), 128, GSMEM>>>(
        WTh, WTl, wqTh, wqTl, zeros, nullptr, Gh, Gl,
        Dsz, Dsz, (long)Dsz * Dsz, 0, (long)Dsz * Dsz, 0);

    // 6) out_b = q_b @ G_b^T + b'  [2048x1024, K=1024] -> fp32
    gemm_mma<<<dim3(Dsz / 128, Ssz / 128, Bsz), 128, GSMEM>>>(
        qh, ql, Gh, Gl, bp, out, nullptr, nullptr,
        Dsz, Dsz, (long)Ssz * Dsz, (long)Dsz * Dsz, (long)Ssz * Dsz, Dsz);
}